// round 2
// baseline (speedup 1.0000x reference)
#include <cuda_runtime.h>

// SparseLayer: 100000 independent tiny linear MLPs (5 -> 2 -> 2 -> 1), batch 128.
// No nonlinearity => per net the chain collapses to a single 1x5 vector
//   v = w2 @ w1 @ w0, out[b] = sum_i v[i] * x[i][b].
// One warp per net; each lane handles 4 batch columns as float4.

#define N_NETS    100000
#define INTERFACE 5
#define BATCH     128

__global__ __launch_bounds__(256) void sparse_layer_kernel(
    const float* __restrict__ x,    // [N_NETS*5, 128]
    const float* __restrict__ w0,   // [N_NETS, 2, 5]
    const float* __restrict__ w1,   // [N_NETS, 2, 2]
    const float* __restrict__ w2,   // [N_NETS, 1, 2]
    float* __restrict__ out)        // [N_NETS, 128]
{
    const int warp = (blockIdx.x * blockDim.x + threadIdx.x) >> 5;
    const int lane = threadIdx.x & 31;
    if (warp >= N_NETS) return;

    // Per-net weights (same address across the warp -> broadcast loads).
    const float* W0 = w0 + (size_t)warp * 10;  // [2,5] row-major
    const float* W1 = w1 + (size_t)warp * 4;   // [2,2] row-major
    const float* W2 = w2 + (size_t)warp * 2;   // [1,2]

    // u = w2 @ w1  (1x2):  u[h] = w2[0]*w1[0][h] + w2[1]*w1[1][h]
    const float a0 = W2[0] * W1[0] + W2[1] * W1[2];
    const float a1 = W2[0] * W1[1] + W2[1] * W1[3];

    // v = u @ w0  (1x5)
    float v[INTERFACE];
#pragma unroll
    for (int i = 0; i < INTERFACE; ++i)
        v[i] = a0 * W0[i] + a1 * W0[INTERFACE + i];

    // Stream this net's x rows; each lane covers 4 contiguous batch columns.
    const float4* xp = reinterpret_cast<const float4*>(
        x + (size_t)warp * INTERFACE * BATCH);

    float4 acc = make_float4(0.f, 0.f, 0.f, 0.f);
#pragma unroll
    for (int i = 0; i < INTERFACE; ++i) {
        float4 xv = xp[i * (BATCH / 4) + lane];
        acc.x = fmaf(v[i], xv.x, acc.x);
        acc.y = fmaf(v[i], xv.y, acc.y);
        acc.z = fmaf(v[i], xv.z, acc.z);
        acc.w = fmaf(v[i], xv.w, acc.w);
    }

    reinterpret_cast<float4*>(out)[(size_t)warp * (BATCH / 4) + lane] = acc;
}

extern "C" void kernel_launch(void* const* d_in, const int* in_sizes, int n_in,
                              void* d_out, int out_size)
{
    const float* x  = (const float*)d_in[0];
    const float* w0 = (const float*)d_in[1];
    const float* w1 = (const float*)d_in[2];
    const float* w2 = (const float*)d_in[3];
    float* out = (float*)d_out;

    const int warps_per_block = 256 / 32;                       // 8 nets per block
    const int grid = (N_NETS + warps_per_block - 1) / warps_per_block;
    sparse_layer_kernel<<<grid, 256>>>(x, w0, w1, w2, out);
}